// round 10
// baseline (speedup 1.0000x reference)
#include <cuda_runtime.h>
#include <cuda_fp16.h>
#include <math_constants.h>
#include <cstdint>

#define D 128
#define MAXN 50048
#define MAXE 400000
#define NB_SCAN 256        // max scan blocks (ceil(50000/256)=196)

// ---------------- scratch (device globals; no allocation allowed) ----------
__device__ float g_qa[MAXN * D];                 // fp32, pre-scaled by 1/sqrt(D)
__device__ float g_qb[MAXN * D];                 // fp32, pre-scaled by 1/sqrt(D)
__device__ __align__(16) __half g_kab[MAXN * 2 * D];  // per node: groups of [ka x4, kb x4]
__device__ __align__(16) __half g_wtx[MAXN * 2 * D];  // per node: groups of [wt x4, wx x4]
__device__ int   g_deg[MAXN];
__device__ int   g_start[MAXN];     // within-scanblock exclusive partial
__device__ int   g_bsum[NB_SCAN];
__device__ int   g_boff[NB_SCAN];   // per-scanblock exclusive offsets
__device__ int   g_done;
__device__ int   g_ecol[MAXE];
__device__ int   g_epos[MAXE];      // within-segment rank from hist

// ---------------- helpers ---------------------------------------------------
__device__ __forceinline__ void mma_fp16(float c[4],
    uint32_t a0, uint32_t a1, uint32_t a2, uint32_t a3,
    uint32_t b0, uint32_t b1)
{
    asm volatile(
        "mma.sync.aligned.m16n8k16.row.col.f32.f16.f16.f32 "
        "{%0,%1,%2,%3}, {%4,%5,%6,%7}, {%8,%9}, {%0,%1,%2,%3};"
        : "+f"(c[0]), "+f"(c[1]), "+f"(c[2]), "+f"(c[3])
        : "r"(a0), "r"(a1), "r"(a2), "r"(a3), "r"(b0), "r"(b1));
}

__device__ __forceinline__ uint32_t ld_f2_h2(const float* p) {
    float2 v = *(const float2*)p;
    __half2 h = __floats2half2_rn(v.x, v.y);
    return *(uint32_t*)&h;
}

// ---------------- CSR build -------------------------------------------------
__global__ void zero_kernel(int N) {
    int i = blockIdx.x * blockDim.x + threadIdx.x;
    if (i < N) g_deg[i] = 0;
    if (i == 0) g_done = 0;
}

// histogram; the atomic's return value is the edge's within-segment rank
__global__ void hist_kernel(const int* __restrict__ row, int E) {
    int e = blockIdx.x * blockDim.x + threadIdx.x;
    if (e < E) g_epos[e] = atomicAdd(&g_deg[row[e]], 1);
}

// scanA + scanB fused: per-block exclusive scan of degrees, last finished
// block scans the per-block sums (threadFenceReduction pattern).
__global__ void scanAB_kernel(int N, int nb) {
    __shared__ int s[256];
    __shared__ bool isLast;
    int tx = threadIdx.x;
    int i = blockIdx.x * 256 + tx;
    int v = (i < N) ? g_deg[i] : 0;
    s[tx] = v;
    __syncthreads();
    #pragma unroll
    for (int off = 1; off < 256; off <<= 1) {
        int t = (tx >= off) ? s[tx - off] : 0;
        __syncthreads();
        s[tx] += t;
        __syncthreads();
    }
    if (i < N) g_start[i] = s[tx] - v;          // exclusive partial
    if (tx == 255) g_bsum[blockIdx.x] = s[255];
    __threadfence();
    __syncthreads();
    if (tx == 0) {
        int d = atomicAdd(&g_done, 1);
        isLast = (d == gridDim.x - 1);
    }
    __syncthreads();
    if (isLast) {
        __threadfence();
        int v2 = (tx < nb) ? g_bsum[tx] : 0;
        s[tx] = v2;
        __syncthreads();
        #pragma unroll
        for (int off = 1; off < 256; off <<= 1) {
            int t = (tx >= off) ? s[tx - off] : 0;
            __syncthreads();
            s[tx] += t;
            __syncthreads();
        }
        if (tx < nb) g_boff[tx] = s[tx] - v2;   // exclusive
    }
}

// atomic-free scatter: final position = start + boff + rank-from-hist
__global__ void scatter_kernel(const int* __restrict__ row,
                               const int* __restrict__ col, int E) {
    int e = blockIdx.x * blockDim.x + threadIdx.x;
    if (e < E) {
        int r = row[e];
        int p = g_start[r] + g_boff[r >> 8] + g_epos[e];
        g_ecol[p] = col[e];
    }
}

// ---------------- fused 3-projection GEMM (A amortized) ----------------------
// Two groups: z=0 uses A=t with {Qaw,Kaw,Wt}; z=1 uses A=x with {Qbw,Kbw,Wx}.
// A fragments loaded ONCE into registers (packed fp16), reused across all
// 3 weight matrices and all 128 output cols.  W staged per-projection in smem.
#define WS_H_STRIDE 136

__global__ __launch_bounds__(256) void gemm3_fp16_kernel(
    const float* __restrict__ x, const float* __restrict__ t,
    const float* __restrict__ Wx, const float* __restrict__ Wt,
    const float* __restrict__ Qaw, const float* __restrict__ Qab,
    const float* __restrict__ Kaw, const float* __restrict__ Kab,
    const float* __restrict__ Qbw, const float* __restrict__ Qbb,
    const float* __restrict__ Kbw, const float* __restrict__ Kbb,
    int N)
{
    const float inv_sqrt_d = 0.088388347648318447f;
    const float* A;
    const float* Wm[3];
    const float* bias[3];
    float* outq;
    int sel;
    if (blockIdx.z == 0) {
        A = t; Wm[0] = Qaw; Wm[1] = Kaw; Wm[2] = Wt;
        bias[0] = Qab; bias[1] = Kab; bias[2] = nullptr;
        outq = g_qa; sel = 0;
    } else {
        A = x; Wm[0] = Qbw; Wm[1] = Kbw; Wm[2] = Wx;
        bias[0] = Qbb; bias[1] = Kbb; bias[2] = nullptr;
        outq = g_qb; sel = 4;
    }

    __shared__ __half Ws[128 * WS_H_STRIDE];   // one W matrix, fp16

    const int tid  = threadIdx.x;
    const int w    = tid >> 5;
    const int lane = tid & 31;
    const int gid  = lane >> 2;   // 0..7
    const int tig  = lane & 3;    // 0..3

    const int rm = blockIdx.x * 128 + w * 16;
    const int r0 = rm + gid;
    const int r1 = r0 + 8;
    const bool v0 = r0 < N;
    const bool v1 = r1 < N;
    const float* A0 = A + (size_t)(v0 ? r0 : 0) * D;
    const float* A1 = A + (size_t)(v1 ? r1 : 0) * D;

    // ---- load A fragments once (packed fp16), reuse for 3 projections ----
    uint32_t afr[8][4];
    #pragma unroll
    for (int kc = 0; kc < 8; kc++) {
        const int k = kc * 16 + 2 * tig;
        afr[kc][0] = v0 ? ld_f2_h2(A0 + k)     : 0u;
        afr[kc][1] = v1 ? ld_f2_h2(A1 + k)     : 0u;
        afr[kc][2] = v0 ? ld_f2_h2(A0 + k + 8) : 0u;
        afr[kc][3] = v1 ? ld_f2_h2(A1 + k + 8) : 0u;
    }

    for (int p = 0; p < 3; p++) {
        // stage W_p (fp32 global -> fp16 smem), stride 136 halves
        __syncthreads();   // previous projection finished reading Ws
        const float* Wp = Wm[p];
        for (int i = tid; i < 128 * 32; i += 256) {
            int r  = i >> 5;
            int c4 = (i & 31) * 4;
            float4 v = *(const float4*)(Wp + (size_t)r * D + c4);
            __half2* dst = (__half2*)&Ws[r * WS_H_STRIDE + c4];
            dst[0] = __floats2half2_rn(v.x, v.y);
            dst[1] = __floats2half2_rn(v.z, v.w);
        }
        __syncthreads();

        const float* bp = bias[p];

        #pragma unroll
        for (int ny = 0; ny < 2; ny++) {
            float c[8][4];
            #pragma unroll
            for (int j = 0; j < 8; j++)
                #pragma unroll
                for (int q = 0; q < 4; q++) c[j][q] = 0.0f;

            #pragma unroll
            for (int kc = 0; kc < 8; kc++) {
                #pragma unroll
                for (int j = 0; j < 8; j++) {
                    const __half* wp =
                        &Ws[(ny * 64 + j * 8 + gid) * WS_H_STRIDE + kc * 16 + 2 * tig];
                    uint32_t b0 = *(const uint32_t*)wp;
                    uint32_t b1 = *(const uint32_t*)(wp + 8);
                    mma_fp16(c[j], afr[kc][0], afr[kc][1], afr[kc][2], afr[kc][3],
                             b0, b1);
                }
            }

            // epilogue
            #pragma unroll
            for (int j = 0; j < 8; j++) {
                int colo = ny * 64 + j * 8 + 2 * tig;   // even
                float b0 = 0.0f, b1 = 0.0f;
                if (bp) { b0 = bp[colo]; b1 = bp[colo + 1]; }
                if (p == 0) {
                    // Q: fp32, pre-scaled by 1/sqrt(D)
                    if (v0) {
                        float2 o = make_float2((c[j][0] + b0) * inv_sqrt_d,
                                               (c[j][1] + b1) * inv_sqrt_d);
                        *(float2*)(outq + (size_t)r0 * D + colo) = o;
                    }
                    if (v1) {
                        float2 o = make_float2((c[j][2] + b0) * inv_sqrt_d,
                                               (c[j][3] + b1) * inv_sqrt_d);
                        *(float2*)(outq + (size_t)r1 * D + colo) = o;
                    }
                } else {
                    __half* outh = (p == 1) ? g_kab : g_wtx;
                    // packed: element d -> half index (d>>2)*8 + sel + (d&3)
                    int goff = ((colo >> 2) << 3) + sel + (colo & 3);
                    if (v0) {
                        __half2 o = __floats2half2_rn(c[j][0] + b0, c[j][1] + b1);
                        *(__half2*)(outh + (size_t)r0 * 2 * D + goff) = o;
                    }
                    if (v1) {
                        __half2 o = __floats2half2_rn(c[j][2] + b0, c[j][3] + b1);
                        *(__half2*)(outh + (size_t)r1 * 2 * D + goff) = o;
                    }
                }
            }
        }
    }
}

// ---------------- CSR edge kernel: one warp per destination node -------------
// Two edges per iteration (4 interleaved shuffle chains, 4 gathers in
// flight) with pair-ahead prefetch. Second edge of an odd pair is index-
// clamped to a valid edge and its contribution masked by 0.
__global__ __launch_bounds__(128) void csr_node_kernel(
    float* __restrict__ out_x, float* __restrict__ out_t, int N)
{
    int r    = (blockIdx.x * blockDim.x + threadIdx.x) >> 5;
    int lane = threadIdx.x & 31;
    if (r >= N) return;

    int base = g_start[r] + g_boff[r >> 8];
    int deg  = g_deg[r];

    const float4 qa = ((const float4*)(g_qa + (size_t)r * D))[lane];
    const float4 qb = ((const float4*)(g_qb + (size_t)r * D))[lane];

    float4 acct = make_float4(0.f, 0.f, 0.f, 0.f);
    float4 accx = make_float4(0.f, 0.f, 0.f, 0.f);
    float suma = 0.0f, sumb = 0.0f;

    uint4 kv0, wv0, kv1, wv1;
    if (deg > 0) {
        int lim = deg - 1;
        int c0 = __ldg(&g_ecol[base]);
        int c1 = __ldg(&g_ecol[base + min(1, lim)]);
        kv0 = *(const uint4*)(g_kab + (size_t)c0 * 2 * D + lane * 8);
        wv0 = *(const uint4*)(g_wtx + (size_t)c0 * 2 * D + lane * 8);
        kv1 = *(const uint4*)(g_kab + (size_t)c1 * 2 * D + lane * 8);
        wv1 = *(const uint4*)(g_wtx + (size_t)c1 * 2 * D + lane * 8);

        for (int i = 0; i < deg; i += 2) {
            uint4 ka_ = kv0, wa_ = wv0, kb_ = kv1, wb_ = wv1;
            float m1 = (i + 1 < deg) ? 1.0f : 0.0f;

            if (i + 2 < deg) {
                int cn0 = __ldg(&g_ecol[base + i + 2]);
                int cn1 = __ldg(&g_ecol[base + min(i + 3, lim)]);
                kv0 = *(const uint4*)(g_kab + (size_t)cn0 * 2 * D + lane * 8);
                wv0 = *(const uint4*)(g_wtx + (size_t)cn0 * 2 * D + lane * 8);
                kv1 = *(const uint4*)(g_kab + (size_t)cn1 * 2 * D + lane * 8);
                wv1 = *(const uint4*)(g_wtx + (size_t)cn1 * 2 * D + lane * 8);
            }

            // edge 0 partials
            float2 e0ka01 = __half22float2(*(__half2*)&ka_.x);
            float2 e0ka23 = __half22float2(*(__half2*)&ka_.y);
            float2 e0kb01 = __half22float2(*(__half2*)&ka_.z);
            float2 e0kb23 = __half22float2(*(__half2*)&ka_.w);
            // edge 1 partials
            float2 e1ka01 = __half22float2(*(__half2*)&kb_.x);
            float2 e1ka23 = __half22float2(*(__half2*)&kb_.y);
            float2 e1kb01 = __half22float2(*(__half2*)&kb_.z);
            float2 e1kb23 = __half22float2(*(__half2*)&kb_.w);

            float sa0 = qa.x * e0ka01.x + qa.y * e0ka01.y + qa.z * e0ka23.x + qa.w * e0ka23.y;
            float sb0 = qb.x * e0kb01.x + qb.y * e0kb01.y + qb.z * e0kb23.x + qb.w * e0kb23.y;
            float sa1 = qa.x * e1ka01.x + qa.y * e1ka01.y + qa.z * e1ka23.x + qa.w * e1ka23.y;
            float sb1 = qb.x * e1kb01.x + qb.y * e1kb01.y + qb.z * e1kb23.x + qb.w * e1kb23.y;

            #pragma unroll
            for (int o = 16; o > 0; o >>= 1) {
                sa0 += __shfl_xor_sync(0xFFFFFFFFu, sa0, o);
                sb0 += __shfl_xor_sync(0xFFFFFFFFu, sb0, o);
                sa1 += __shfl_xor_sync(0xFFFFFFFFu, sa1, o);
                sb1 += __shfl_xor_sync(0xFFFFFFFFu, sb1, o);
            }

            // qa/qb pre-scaled by 1/sqrt(D); scores O(0.5): softmax is
            // shift-invariant and exp can't overflow -> no max pass.
            float ea0 = __expf(sa0);
            float eb0 = __expf(sb0);
            float ea1 = __expf(sa1) * m1;
            float eb1 = __expf(sb1) * m1;
            suma += ea0 + ea1;
            sumb += eb0 + eb1;

            float2 wt01 = __half22float2(*(__half2*)&wa_.x);
            float2 wt23 = __half22float2(*(__half2*)&wa_.y);
            float2 wx01 = __half22float2(*(__half2*)&wa_.z);
            float2 wx23 = __half22float2(*(__half2*)&wa_.w);
            float2 ut01 = __half22float2(*(__half2*)&wb_.x);
            float2 ut23 = __half22float2(*(__half2*)&wb_.y);
            float2 ux01 = __half22float2(*(__half2*)&wb_.z);
            float2 ux23 = __half22float2(*(__half2*)&wb_.w);

            acct.x += ea0 * wt01.x + ea1 * ut01.x;
            acct.y += ea0 * wt01.y + ea1 * ut01.y;
            acct.z += ea0 * wt23.x + ea1 * ut23.x;
            acct.w += ea0 * wt23.y + ea1 * ut23.y;
            accx.x += eb0 * wx01.x + eb1 * ux01.x;
            accx.y += eb0 * wx01.y + eb1 * ux01.y;
            accx.z += eb0 * wx23.x + eb1 * ux23.x;
            accx.w += eb0 * wx23.y + eb1 * ux23.y;
        }
    }

    // deg==0 -> sums are 0 -> write exact zeros (matches empty segment_sum)
    float ia = (suma > 0.0f) ? 1.0f / suma : 0.0f;
    float ib = (sumb > 0.0f) ? 1.0f / sumb : 0.0f;
    acct.x *= ia; acct.y *= ia; acct.z *= ia; acct.w *= ia;
    accx.x *= ib; accx.y *= ib; accx.z *= ib; accx.w *= ib;

    ((float4*)(out_t + (size_t)r * D))[lane] = acct;
    ((float4*)(out_x + (size_t)r * D))[lane] = accx;
}

// ---------------- launcher ---------------------------------------------------
extern "C" void kernel_launch(void* const* d_in, const int* in_sizes, int n_in,
                              void* d_out, int out_size)
{
    const float* x   = (const float*)d_in[0];
    const float* t   = (const float*)d_in[1];
    const int*   ei  = (const int*)  d_in[2];
    const float* Wx  = (const float*)d_in[3];
    const float* Wt  = (const float*)d_in[4];
    const float* Qaw = (const float*)d_in[5];
    const float* Qab = (const float*)d_in[6];
    const float* Kaw = (const float*)d_in[7];
    const float* Kab = (const float*)d_in[8];
    const float* Qbw = (const float*)d_in[9];
    const float* Qbb = (const float*)d_in[10];
    const float* Kbw = (const float*)d_in[11];
    const float* Kbb = (const float*)d_in[12];

    int N = in_sizes[0] / D;
    int E = in_sizes[2] / 2;
    const int* row = ei;        // dest
    const int* col = ei + E;    // src

    float* out_x = (float*)d_out;
    float* out_t = (float*)d_out + (size_t)N * D;

    int nbScan = (N + 255) / 256;

    // --- CSR build (4 kernels; scatter is atomic-free via hist ranks) ---
    zero_kernel<<<nbScan, 256>>>(N);
    hist_kernel<<<(E + 255) / 256, 256>>>(row, E);
    scanAB_kernel<<<nbScan, 256>>>(N, nbScan);
    scatter_kernel<<<(E + 255) / 256, 256>>>(row, col, E);

    // --- six node projections: 2 groups x 3 shared-A projections ---
    {
        dim3 grid((N + 127) / 128, 1, 2);
        gemm3_fp16_kernel<<<grid, 256>>>(x, t, Wx, Wt, Qaw, Qab, Kaw, Kab,
                                         Qbw, Qbb, Kbw, Kbb, N);
    }

    // --- CSR edge pass: warp per destination, atomic-free, 2-edge pipeline ---
    csr_node_kernel<<<(N + 3) / 4, 128>>>(out_x, out_t, N);
}

// round 11
// speedup vs baseline: 1.2206x; 1.2206x over previous
#include <cuda_runtime.h>
#include <cuda_fp16.h>
#include <math_constants.h>
#include <cstdint>

#define D 128
#define MAXN 50048
#define MAXE 400000
#define NB_SCAN 256        // max scan blocks (ceil(50000/256)=196)
#define WS_H_STRIDE 136

// ---------------- scratch (device globals; no allocation allowed) ----------
__device__ float g_qa[MAXN * D];                 // fp32, pre-scaled by 1/sqrt(D)
__device__ float g_qb[MAXN * D];                 // fp32, pre-scaled by 1/sqrt(D)
__device__ __align__(16) __half g_kab[MAXN * 2 * D];  // per node: groups of [ka x4, kb x4]
__device__ __align__(16) __half g_wtx[MAXN * 2 * D];  // per node: groups of [wt x4, wx x4]
__device__ __align__(16) __half g_wh[6 * 128 * WS_H_STRIDE];  // fp16 weights, stride 136
__device__ int   g_deg[MAXN];
__device__ int   g_start[MAXN];     // within-scanblock exclusive partial
__device__ int   g_bsum[NB_SCAN];
__device__ int   g_boff[NB_SCAN];   // per-scanblock exclusive offsets
__device__ int   g_done;
__device__ int   g_ecol[MAXE];
__device__ int   g_epos[MAXE];      // within-segment rank from hist

// ---------------- helpers ---------------------------------------------------
__device__ __forceinline__ void mma_fp16(float c[4],
    uint32_t a0, uint32_t a1, uint32_t a2, uint32_t a3,
    uint32_t b0, uint32_t b1)
{
    asm volatile(
        "mma.sync.aligned.m16n8k16.row.col.f32.f16.f16.f32 "
        "{%0,%1,%2,%3}, {%4,%5,%6,%7}, {%8,%9}, {%0,%1,%2,%3};"
        : "+f"(c[0]), "+f"(c[1]), "+f"(c[2]), "+f"(c[3])
        : "r"(a0), "r"(a1), "r"(a2), "r"(a3), "r"(b0), "r"(b1));
}

__device__ __forceinline__ uint32_t ld_f2_h2(const float* p) {
    float2 v = *(const float2*)p;
    __half2 h = __floats2half2_rn(v.x, v.y);
    return *(uint32_t*)&h;
}

// ---------------- CSR build -------------------------------------------------
__global__ void zero_kernel(int N) {
    int i = blockIdx.x * blockDim.x + threadIdx.x;
    if (i < N) g_deg[i] = 0;
    if (i == 0) g_done = 0;
}

// histogram; the atomic's return value is the edge's within-segment rank
__global__ void hist_kernel(const int* __restrict__ row, int E) {
    int e = blockIdx.x * blockDim.x + threadIdx.x;
    if (e < E) g_epos[e] = atomicAdd(&g_deg[row[e]], 1);
}

// scanA + scanB fused: per-block exclusive scan of degrees, last finished
// block scans the per-block sums (threadFenceReduction pattern).
__global__ void scanAB_kernel(int N, int nb) {
    __shared__ int s[256];
    __shared__ bool isLast;
    int tx = threadIdx.x;
    int i = blockIdx.x * 256 + tx;
    int v = (i < N) ? g_deg[i] : 0;
    s[tx] = v;
    __syncthreads();
    #pragma unroll
    for (int off = 1; off < 256; off <<= 1) {
        int t = (tx >= off) ? s[tx - off] : 0;
        __syncthreads();
        s[tx] += t;
        __syncthreads();
    }
    if (i < N) g_start[i] = s[tx] - v;          // exclusive partial
    if (tx == 255) g_bsum[blockIdx.x] = s[255];
    __threadfence();
    __syncthreads();
    if (tx == 0) {
        int d = atomicAdd(&g_done, 1);
        isLast = (d == gridDim.x - 1);
    }
    __syncthreads();
    if (isLast) {
        __threadfence();
        int v2 = (tx < nb) ? g_bsum[tx] : 0;
        s[tx] = v2;
        __syncthreads();
        #pragma unroll
        for (int off = 1; off < 256; off <<= 1) {
            int t = (tx >= off) ? s[tx - off] : 0;
            __syncthreads();
            s[tx] += t;
            __syncthreads();
        }
        if (tx < nb) g_boff[tx] = s[tx] - v2;   // exclusive
    }
}

// atomic-free scatter: final position = start + boff + rank-from-hist
__global__ void scatter_kernel(const int* __restrict__ row,
                               const int* __restrict__ col, int E) {
    int e = blockIdx.x * blockDim.x + threadIdx.x;
    if (e < E) {
        int r = row[e];
        int p = g_start[r] + g_boff[r >> 8] + g_epos[e];
        g_ecol[p] = col[e];
    }
}

// ---------------- W -> fp16 pre-conversion (once, global) --------------------
// order: 0=Qaw 1=Kaw 2=Wt (group t), 3=Qbw 4=Kbw 5=Wx (group x)
__global__ void wprep_kernel(
    const float* __restrict__ Qaw, const float* __restrict__ Kaw,
    const float* __restrict__ Wt,  const float* __restrict__ Qbw,
    const float* __restrict__ Kbw, const float* __restrict__ Wx)
{
    const float* W;
    switch (blockIdx.x) {
        case 0: W = Qaw; break;
        case 1: W = Kaw; break;
        case 2: W = Wt;  break;
        case 3: W = Qbw; break;
        case 4: W = Kbw; break;
        default: W = Wx; break;
    }
    __half* dst = g_wh + (size_t)blockIdx.x * 128 * WS_H_STRIDE;
    int r0 = blockIdx.y * 32;            // 32 rows per y-block
    for (int i = threadIdx.x; i < 32 * 32; i += 256) {
        int r  = r0 + (i >> 5);
        int c4 = (i & 31) * 4;
        float4 v = *(const float4*)(W + (size_t)r * D + c4);
        __half2* d = (__half2*)&dst[r * WS_H_STRIDE + c4];
        d[0] = __floats2half2_rn(v.x, v.y);
        d[1] = __floats2half2_rn(v.z, v.w);
    }
}

// ---------------- fused 3-projection GEMM (A amortized, 256 rows/block) ------
// z=0: A=t with {Qaw,Kaw,Wt}; z=1: A=x with {Qbw,Kbw,Wx}.
// A fragments for BOTH 128-row tiles live in registers; each B fragment pair
// is loaded once from smem and feeds 2 MMAs (one per row tile).
__global__ __launch_bounds__(256) void gemm3_fp16_kernel(
    const float* __restrict__ x, const float* __restrict__ t,
    const float* __restrict__ Qab, const float* __restrict__ Kab,
    const float* __restrict__ Qbb, const float* __restrict__ Kbb,
    int N)
{
    const float inv_sqrt_d = 0.088388347648318447f;
    const float* A;
    const float* bias[3];
    float* outq;
    int sel;
    if (blockIdx.z == 0) {
        A = t; bias[0] = Qab; bias[1] = Kab; bias[2] = nullptr;
        outq = g_qa; sel = 0;
    } else {
        A = x; bias[0] = Qbb; bias[1] = Kbb; bias[2] = nullptr;
        outq = g_qb; sel = 4;
    }

    __shared__ __half Ws[128 * WS_H_STRIDE];   // one W matrix, fp16

    const int tid  = threadIdx.x;
    const int w    = tid >> 5;
    const int lane = tid & 31;
    const int gid  = lane >> 2;   // 0..7
    const int tig  = lane & 3;    // 0..3

    const int rm = blockIdx.x * 256 + w * 16;

    // rows for the two 128-row tiles
    int rr[2][2];
    bool vv[2][2];
    const float* Ap[2][2];
    #pragma unroll
    for (int rt = 0; rt < 2; rt++) {
        rr[rt][0] = rm + rt * 128 + gid;
        rr[rt][1] = rr[rt][0] + 8;
        vv[rt][0] = rr[rt][0] < N;
        vv[rt][1] = rr[rt][1] < N;
        Ap[rt][0] = A + (size_t)(vv[rt][0] ? rr[rt][0] : 0) * D;
        Ap[rt][1] = A + (size_t)(vv[rt][1] ? rr[rt][1] : 0) * D;
    }

    // ---- load A fragments once (packed fp16), both tiles ----
    uint32_t afr[2][8][4];
    #pragma unroll
    for (int rt = 0; rt < 2; rt++)
        #pragma unroll
        for (int kc = 0; kc < 8; kc++) {
            const int k = kc * 16 + 2 * tig;
            afr[rt][kc][0] = vv[rt][0] ? ld_f2_h2(Ap[rt][0] + k)     : 0u;
            afr[rt][kc][1] = vv[rt][1] ? ld_f2_h2(Ap[rt][1] + k)     : 0u;
            afr[rt][kc][2] = vv[rt][0] ? ld_f2_h2(Ap[rt][0] + k + 8) : 0u;
            afr[rt][kc][3] = vv[rt][1] ? ld_f2_h2(Ap[rt][1] + k + 8) : 0u;
        }

    for (int p = 0; p < 3; p++) {
        // stage W_p: straight uint4 copy from pre-converted fp16 global
        __syncthreads();   // previous projection finished reading Ws
        const uint4* src = (const uint4*)(g_wh +
                            (size_t)(blockIdx.z * 3 + p) * 128 * WS_H_STRIDE);
        uint4* dst = (uint4*)Ws;
        for (int i = tid; i < 128 * (WS_H_STRIDE / 8); i += 256)
            dst[i] = src[i];
        __syncthreads();

        const float* bp = bias[p];

        #pragma unroll
        for (int ny = 0; ny < 2; ny++) {
            float c0[8][4], c1[8][4];
            #pragma unroll
            for (int j = 0; j < 8; j++)
                #pragma unroll
                for (int q = 0; q < 4; q++) { c0[j][q] = 0.0f; c1[j][q] = 0.0f; }

            #pragma unroll
            for (int kc = 0; kc < 8; kc++) {
                #pragma unroll
                for (int j = 0; j < 8; j++) {
                    const __half* wp =
                        &Ws[(ny * 64 + j * 8 + gid) * WS_H_STRIDE + kc * 16 + 2 * tig];
                    uint32_t b0 = *(const uint32_t*)wp;
                    uint32_t b1 = *(const uint32_t*)(wp + 8);
                    mma_fp16(c0[j], afr[0][kc][0], afr[0][kc][1],
                                    afr[0][kc][2], afr[0][kc][3], b0, b1);
                    mma_fp16(c1[j], afr[1][kc][0], afr[1][kc][1],
                                    afr[1][kc][2], afr[1][kc][3], b0, b1);
                }
            }

            // epilogue, both tiles
            #pragma unroll
            for (int j = 0; j < 8; j++) {
                int colo = ny * 64 + j * 8 + 2 * tig;   // even
                float b0 = 0.0f, b1 = 0.0f;
                if (bp) { b0 = bp[colo]; b1 = bp[colo + 1]; }
                #pragma unroll
                for (int rt = 0; rt < 2; rt++) {
                    const float* cj = (rt == 0) ? c0[j] : c1[j];
                    if (p == 0) {
                        if (vv[rt][0]) {
                            float2 o = make_float2((cj[0] + b0) * inv_sqrt_d,
                                                   (cj[1] + b1) * inv_sqrt_d);
                            *(float2*)(outq + (size_t)rr[rt][0] * D + colo) = o;
                        }
                        if (vv[rt][1]) {
                            float2 o = make_float2((cj[2] + b0) * inv_sqrt_d,
                                                   (cj[3] + b1) * inv_sqrt_d);
                            *(float2*)(outq + (size_t)rr[rt][1] * D + colo) = o;
                        }
                    } else {
                        __half* outh = (p == 1) ? g_kab : g_wtx;
                        int goff = ((colo >> 2) << 3) + sel + (colo & 3);
                        if (vv[rt][0]) {
                            __half2 o = __floats2half2_rn(cj[0] + b0, cj[1] + b1);
                            *(__half2*)(outh + (size_t)rr[rt][0] * 2 * D + goff) = o;
                        }
                        if (vv[rt][1]) {
                            __half2 o = __floats2half2_rn(cj[2] + b0, cj[3] + b1);
                            *(__half2*)(outh + (size_t)rr[rt][1] * 2 * D + goff) = o;
                        }
                    }
                }
            }
        }
    }
}

// ---------------- CSR edge kernel: one warp per destination node -------------
// Depth-1 software pipeline: next edge's index + gathers issued before the
// current edge's compute, hiding L2 latency behind shuffles/exp/FMA.
__global__ __launch_bounds__(128) void csr_node_kernel(
    float* __restrict__ out_x, float* __restrict__ out_t, int N)
{
    int r    = (blockIdx.x * blockDim.x + threadIdx.x) >> 5;
    int lane = threadIdx.x & 31;
    if (r >= N) return;

    int base = g_start[r] + g_boff[r >> 8];
    int deg  = g_deg[r];

    const float4 qa = ((const float4*)(g_qa + (size_t)r * D))[lane];
    const float4 qb = ((const float4*)(g_qb + (size_t)r * D))[lane];

    float4 acct = make_float4(0.f, 0.f, 0.f, 0.f);
    float4 accx = make_float4(0.f, 0.f, 0.f, 0.f);
    float suma = 0.0f, sumb = 0.0f;

    uint4 kv, wv;
    if (deg > 0) {
        int c0 = __ldg(&g_ecol[base]);
        kv = *(const uint4*)(g_kab + (size_t)c0 * 2 * D + lane * 8);
        wv = *(const uint4*)(g_wtx + (size_t)c0 * 2 * D + lane * 8);
    }

    for (int i = 0; i < deg; i++) {
        uint4 kvc = kv, wvc = wv;
        if (i + 1 < deg) {
            int cn = __ldg(&g_ecol[base + i + 1]);
            kv = *(const uint4*)(g_kab + (size_t)cn * 2 * D + lane * 8);
            wv = *(const uint4*)(g_wtx + (size_t)cn * 2 * D + lane * 8);
        }

        float2 ka01 = __half22float2(*(__half2*)&kvc.x);
        float2 ka23 = __half22float2(*(__half2*)&kvc.y);
        float2 kb01 = __half22float2(*(__half2*)&kvc.z);
        float2 kb23 = __half22float2(*(__half2*)&kvc.w);

        float sa = qa.x * ka01.x + qa.y * ka01.y + qa.z * ka23.x + qa.w * ka23.y;
        float sb = qb.x * kb01.x + qb.y * kb01.y + qb.z * kb23.x + qb.w * kb23.y;
        #pragma unroll
        for (int o = 16; o > 0; o >>= 1) {
            sa += __shfl_xor_sync(0xFFFFFFFFu, sa, o);
            sb += __shfl_xor_sync(0xFFFFFFFFu, sb, o);
        }

        // qa/qb pre-scaled by 1/sqrt(D); scores O(0.5): softmax is
        // shift-invariant and exp can't overflow -> no segment-max pass.
        float ea = __expf(sa);
        float eb = __expf(sb);
        suma += ea;
        sumb += eb;

        float2 wt01 = __half22float2(*(__half2*)&wvc.x);
        float2 wt23 = __half22float2(*(__half2*)&wvc.y);
        float2 wx01 = __half22float2(*(__half2*)&wvc.z);
        float2 wx23 = __half22float2(*(__half2*)&wvc.w);

        acct.x += ea * wt01.x; acct.y += ea * wt01.y;
        acct.z += ea * wt23.x; acct.w += ea * wt23.y;
        accx.x += eb * wx01.x; accx.y += eb * wx01.y;
        accx.z += eb * wx23.x; accx.w += eb * wx23.y;
    }

    // deg==0 -> sums are 0 -> write exact zeros (matches empty segment_sum)
    float ia = (suma > 0.0f) ? 1.0f / suma : 0.0f;
    float ib = (sumb > 0.0f) ? 1.0f / sumb : 0.0f;
    acct.x *= ia; acct.y *= ia; acct.z *= ia; acct.w *= ia;
    accx.x *= ib; accx.y *= ib; accx.z *= ib; accx.w *= ib;

    ((float4*)(out_t + (size_t)r * D))[lane] = acct;
    ((float4*)(out_x + (size_t)r * D))[lane] = accx;
}

// ---------------- launcher ---------------------------------------------------
extern "C" void kernel_launch(void* const* d_in, const int* in_sizes, int n_in,
                              void* d_out, int out_size)
{
    const float* x   = (const float*)d_in[0];
    const float* t   = (const float*)d_in[1];
    const int*   ei  = (const int*)  d_in[2];
    const float* Wx  = (const float*)d_in[3];
    const float* Wt  = (const float*)d_in[4];
    const float* Qaw = (const float*)d_in[5];
    const float* Qab = (const float*)d_in[6];
    const float* Kaw = (const float*)d_in[7];
    const float* Kab = (const float*)d_in[8];
    const float* Qbw = (const float*)d_in[9];
    const float* Qbb = (const float*)d_in[10];
    const float* Kbw = (const float*)d_in[11];
    const float* Kbb = (const float*)d_in[12];

    int N = in_sizes[0] / D;
    int E = in_sizes[2] / 2;
    const int* row = ei;        // dest
    const int* col = ei + E;    // src

    float* out_x = (float*)d_out;
    float* out_t = (float*)d_out + (size_t)N * D;

    int nbScan = (N + 255) / 256;

    // --- W fp16 pre-conversion (tiny) ---
    {
        dim3 grid(6, 4);
        wprep_kernel<<<grid, 256>>>(Qaw, Kaw, Wt, Qbw, Kbw, Wx);
    }

    // --- CSR build (atomic-free scatter via hist ranks) ---
    zero_kernel<<<nbScan, 256>>>(N);
    hist_kernel<<<(E + 255) / 256, 256>>>(row, E);
    scanAB_kernel<<<nbScan, 256>>>(N, nbScan);
    scatter_kernel<<<(E + 255) / 256, 256>>>(row, col, E);

    // --- six node projections: 2 groups x 3 shared-A projections ---
    {
        dim3 grid((N + 255) / 256, 1, 2);
        gemm3_fp16_kernel<<<grid, 256>>>(x, t, Qab, Kab, Qbb, Kbb, N);
    }

    // --- CSR edge pass: warp per destination, atomic-free, pipelined ---
    csr_node_kernel<<<(N + 3) / 4, 128>>>(out_x, out_t, N);
}